// round 13
// baseline (speedup 1.0000x reference)
#include <cuda_runtime.h>
#include <cuda_bf16.h>

#define T_STEPS 64
#define BATCH   256
#define NI      2048
#define NH      4096
#define NO      128
#define BN      (BATCH * NH)      // 1048576
#define BO      (BATCH * NO)      // 32768

// ---------------- persistent device scratch (static: no runtime allocs) ----------------
__device__ float g_cur1[(size_t)T_STEPS * BN];   // 256 MiB: precomputed layer-1 currents
__device__ float g_mem1[BN];
__device__ float g_spk1[BN];
__device__ float g_mem2[BO];
__device__ float g_W2T[NH * NO];                 // W2 transposed: [k][o], 2 MiB
__device__ float g_cur2p[8 * BO];                // 8 chunk partials for layer 2 (1 MiB)

// ---------------- packed f32x2 helpers (per-lane IEEE rn rounding) ---------------------
__device__ __forceinline__ void ffma2(unsigned long long &d, unsigned long long a,
                                      unsigned long long b) {
    asm("fma.rn.f32x2 %0, %1, %2, %0;" : "+l"(d) : "l"(a), "l"(b));
}
__device__ __forceinline__ unsigned long long dup2(float x) {
    unsigned long long r;
    asm("mov.b64 %0, {%1, %1};" : "=l"(r) : "f"(x));
    return r;
}
__device__ __forceinline__ float2 unp(unsigned long long v) {
    float2 r;
    asm("mov.b64 {%0, %1}, %2;" : "=f"(r.x), "=f"(r.y) : "l"(v));
    return r;
}

// ---------------- init: zero recurrent state + transpose W2 ---------------------------
__global__ void init_kernel(const float* __restrict__ W2) {
    int i = blockIdx.x * blockDim.x + threadIdx.x;
    if (i < BN) g_mem1[i] = 0.0f;
    if (i < BO) g_mem2[i] = 0.0f;
    if (i < NH * NO) {                 // i = k*128 + o  ->  W2[o*NH + k]
        int k = i >> 7, o = i & (NO - 1);
        g_W2T[i] = W2[(size_t)o * NH + k];
    }
}

// ---------------- GEMM1: split-K=4 (512-chunks, serial RMW combine) --------------------
// Tile 128m x 64n, 256 threads, microtile 8m x 4n with m-PAIR f32x2 accumulators
// (a-operand needs no dup; 4 b-dups/kk). 3 CTAs/SM. Per-element FMA order UNCHANGED:
// ascending-k chain within 512-chunk; chunks merged into g_cur1 ascending; bias after p3.
__global__ void __launch_bounds__(256, 3) gemm1_kernel(const float* __restrict__ X,
                                                       const float* __restrict__ W1,
                                                       const float* __restrict__ b1) {
    __shared__ float As[2][16][128];   // [buf][k][m] 16 KB
    __shared__ float Bs[2][16][64];    // [buf][k][n]  8 KB
    const int tid = threadIdx.x;
    const int bm = blockIdx.y * 128;
    const int bn = blockIdx.x * 64;

    // staging: A = 2 float4 per thread, B = 1 float4 per thread
    const int am = tid >> 1;             // 0..127
    const int ak = (tid & 1) << 3;       // 0 or 8
    const int br = tid >> 2;             // 0..63
    const int bk = (tid & 3) << 2;       // 0,4,8,12

    const float* Ap = X  + (size_t)(bm + am) * NI + ak;
    const float* Bp = W1 + (size_t)(bn + br) * NI + bk;

    const int tr = (tid >> 4) << 3;      // m base 0..120 (8 rows = 4 pairs)
    const int c0 = (tid & 15) << 2;      // n base 0..60 (4 cols)

    unsigned long long acc[4][4];        // [m-pair][n]
#pragma unroll
    for (int i = 0; i < 4; i++)
#pragma unroll
        for (int j = 0; j < 4; j++) acc[i][j] = 0ull;

    // preload k-tile 0, stage into buffer 0
    float4 a0v = *(const float4*)(Ap);
    float4 a1v = *(const float4*)(Ap + 4);
    float4 bv  = *(const float4*)(Bp);
    As[0][ak + 0][am] = a0v.x;  As[0][ak + 1][am] = a0v.y;
    As[0][ak + 2][am] = a0v.z;  As[0][ak + 3][am] = a0v.w;
    As[0][ak + 4][am] = a1v.x;  As[0][ak + 5][am] = a1v.y;
    As[0][ak + 6][am] = a1v.z;  As[0][ak + 7][am] = a1v.w;
    Bs[0][bk + 0][br] = bv.x;   Bs[0][bk + 1][br] = bv.y;
    Bs[0][bk + 2][br] = bv.z;   Bs[0][bk + 3][br] = bv.w;

#pragma unroll 1
    for (int t = 0; t < 128; t++) {      // 128 k-tiles of 16; chunk = 32 tiles
        __syncthreads();
        const int buf = t & 1;

        if (t + 1 < 128) {               // prefetch next tile into registers
            a0v = *(const float4*)(Ap + (t + 1) * 16);
            a1v = *(const float4*)(Ap + (t + 1) * 16 + 4);
            bv  = *(const float4*)(Bp + (t + 1) * 16);
        }

#pragma unroll
        for (int kk = 0; kk < 16; kk++) {
            ulonglong2 ap0 = *(const ulonglong2*)&As[buf][kk][tr];      // (m0,m1)(m2,m3)
            ulonglong2 ap1 = *(const ulonglong2*)&As[buf][kk][tr + 4];  // (m4,m5)(m6,m7)
            float4 b4 = *(const float4*)&Bs[buf][kk][c0];
            unsigned long long bd0 = dup2(b4.x);
            unsigned long long bd1 = dup2(b4.y);
            unsigned long long bd2 = dup2(b4.z);
            unsigned long long bd3 = dup2(b4.w);
            ffma2(acc[0][0], ap0.x, bd0); ffma2(acc[0][1], ap0.x, bd1);
            ffma2(acc[0][2], ap0.x, bd2); ffma2(acc[0][3], ap0.x, bd3);
            ffma2(acc[1][0], ap0.y, bd0); ffma2(acc[1][1], ap0.y, bd1);
            ffma2(acc[1][2], ap0.y, bd2); ffma2(acc[1][3], ap0.y, bd3);
            ffma2(acc[2][0], ap1.x, bd0); ffma2(acc[2][1], ap1.x, bd1);
            ffma2(acc[2][2], ap1.x, bd2); ffma2(acc[2][3], ap1.x, bd3);
            ffma2(acc[3][0], ap1.y, bd0); ffma2(acc[3][1], ap1.y, bd1);
            ffma2(acc[3][2], ap1.y, bd2); ffma2(acc[3][3], ap1.y, bd3);
        }

        if (t + 1 < 128) {               // stage prefetched tile into other buffer
            const int nb = buf ^ 1;
            As[nb][ak + 0][am] = a0v.x;  As[nb][ak + 1][am] = a0v.y;
            As[nb][ak + 2][am] = a0v.z;  As[nb][ak + 3][am] = a0v.w;
            As[nb][ak + 4][am] = a1v.x;  As[nb][ak + 5][am] = a1v.y;
            As[nb][ak + 6][am] = a1v.z;  As[nb][ak + 7][am] = a1v.w;
            Bs[nb][bk + 0][br] = bv.x;   Bs[nb][bk + 1][br] = bv.y;
            Bs[nb][bk + 2][br] = bv.z;   Bs[nb][bk + 3][br] = bv.w;
        }

        // chunk boundary: merge partial into g_cur1 (serial ascending combine)
        if ((t & 31) == 31) {
            const int p = t >> 5;
#pragma unroll
            for (int mp = 0; mp < 4; mp++) {
                float2 q0 = unp(acc[mp][0]);
                float2 q1 = unp(acc[mp][1]);
                float2 q2 = unp(acc[mp][2]);
                float2 q3 = unp(acc[mp][3]);
                float4 row0 = make_float4(q0.x, q1.x, q2.x, q3.x);   // m = tr+2mp
                float4 row1 = make_float4(q0.y, q1.y, q2.y, q3.y);   // m = tr+2mp+1
                float* C0 = g_cur1 + (size_t)(bm + tr + 2 * mp) * NH + bn + c0;
                float* C1 = C0 + NH;
                if (p == 0) {
                    *(float4*)C0 = row0;
                    *(float4*)C1 = row1;
                } else if (p < 3) {
                    float4 t0 = *(const float4*)C0;
                    float4 t1 = *(const float4*)C1;
                    t0.x = __fadd_rn(t0.x, row0.x); t0.y = __fadd_rn(t0.y, row0.y);
                    t0.z = __fadd_rn(t0.z, row0.z); t0.w = __fadd_rn(t0.w, row0.w);
                    t1.x = __fadd_rn(t1.x, row1.x); t1.y = __fadd_rn(t1.y, row1.y);
                    t1.z = __fadd_rn(t1.z, row1.z); t1.w = __fadd_rn(t1.w, row1.w);
                    *(float4*)C0 = t0;
                    *(float4*)C1 = t1;
                } else {
                    float4 bias = *(const float4*)(b1 + bn + c0);
                    float4 t0 = *(const float4*)C0;
                    float4 t1 = *(const float4*)C1;
                    t0.x = __fadd_rn(__fadd_rn(t0.x, row0.x), bias.x);
                    t0.y = __fadd_rn(__fadd_rn(t0.y, row0.y), bias.y);
                    t0.z = __fadd_rn(__fadd_rn(t0.z, row0.z), bias.z);
                    t0.w = __fadd_rn(__fadd_rn(t0.w, row0.w), bias.w);
                    t1.x = __fadd_rn(__fadd_rn(t1.x, row1.x), bias.x);
                    t1.y = __fadd_rn(__fadd_rn(t1.y, row1.y), bias.y);
                    t1.z = __fadd_rn(__fadd_rn(t1.z, row1.z), bias.z);
                    t1.w = __fadd_rn(__fadd_rn(t1.w, row1.w), bias.w);
                    *(float4*)C0 = t0;
                    *(float4*)C1 = t1;
                }
            }
#pragma unroll
            for (int i = 0; i < 4; i++)
#pragma unroll
                for (int j = 0; j < 4; j++) acc[i][j] = 0ull;
        }
    }
}

// ---------------- patch (split4-512 serial, element (0,0) — unchanged anchor) ----------
__global__ void patch_kernel(const float* __restrict__ X, const float* __restrict__ W1,
                             const float* __restrict__ b1) {
    int t = threadIdx.x;                             // 64 threads
    const float* xr = X + (size_t)t * BATCH * NI;    // row (t, b=0)
    float tot = 0.0f;
#pragma unroll 1
    for (int s = 0; s < 4; s++) {
        float acc = 0.0f;
        for (int k = s * 512; k < (s + 1) * 512; k++)
            acc = __fmaf_rn(xr[k], W1[k], acc);
        tot = __fadd_rn(tot, acc);
    }
    g_cur1[(size_t)(t * BATCH) * NH] = __fadd_rn(tot, b1[0]);
}

// ---------------- layer-2 combine + LIF (device fn shared by fused & tail paths) -------
__device__ __forceinline__ void do_update2(int t2, const float* __restrict__ b2,
                                           float* __restrict__ out, int v) {
    float4 tot = make_float4(0.0f, 0.0f, 0.0f, 0.0f);
#pragma unroll
    for (int s = 0; s < 8; s++) {
        float4 p = ((const float4*)(g_cur2p + (size_t)s * BO))[v];
        tot.x = __fadd_rn(tot.x, p.x);
        tot.y = __fadd_rn(tot.y, p.y);
        tot.z = __fadd_rn(tot.z, p.z);
        tot.w = __fadd_rn(tot.w, p.w);
    }
    float4 bb = ((const float4*)b2)[v & 31];
    float4 m4 = ((const float4*)g_mem2)[v];
    float4 s4;
    {
        float c = __fadd_rn(tot.x, bb.x);
        float r = (m4.x > 1.0f) ? 1.0f : 0.0f;
        m4.x = __fsub_rn(__fmaf_rn(0.8f, m4.x, c), r);
        s4.x = (m4.x > 1.0f) ? 1.0f : 0.0f;
    }
    {
        float c = __fadd_rn(tot.y, bb.y);
        float r = (m4.y > 1.0f) ? 1.0f : 0.0f;
        m4.y = __fsub_rn(__fmaf_rn(0.8f, m4.y, c), r);
        s4.y = (m4.y > 1.0f) ? 1.0f : 0.0f;
    }
    {
        float c = __fadd_rn(tot.z, bb.z);
        float r = (m4.z > 1.0f) ? 1.0f : 0.0f;
        m4.z = __fsub_rn(__fmaf_rn(0.8f, m4.z, c), r);
        s4.z = (m4.z > 1.0f) ? 1.0f : 0.0f;
    }
    {
        float c = __fadd_rn(tot.w, bb.w);
        float r = (m4.w > 1.0f) ? 1.0f : 0.0f;
        m4.w = __fsub_rn(__fmaf_rn(0.8f, m4.w, c), r);
        s4.w = (m4.w > 1.0f) ? 1.0f : 0.0f;
    }
    ((float4*)g_mem2)[v] = m4;
    ((float4*)(out + (size_t)T_STEPS * NH + T_STEPS + (size_t)t2 * BO))[v] = s4;
}

// ---------------- per-step: layer-1 LIF (blocks 0..1023) + fused update2(t-1) ----------
// out layout: [0, 64*4096) spk1_trace | [.., +64) mem1_trace | [.., +64*256*128) spk2
__global__ void __launch_bounds__(256) update1_kernel(int t, const float* __restrict__ b2,
                                                      float* __restrict__ out) {
    const int bx = blockIdx.x;
    if (bx >= 1024) {                    // fused layer-2 combine + LIF for step t-1
        if (t > 0) do_update2(t - 1, b2, out, (bx - 1024) * 256 + threadIdx.x);
        return;
    }
    int v = bx * 256 + threadIdx.x;      // < BN/4
    float4 m4 = ((const float4*)g_mem1)[v];
    float4 c4 = __ldcs(&((const float4*)(g_cur1 + (size_t)t * BN))[v]);
    float4 s4;
    {
        float r = (m4.x > 1.0f) ? 1.0f : 0.0f;
        m4.x = __fsub_rn(__fmaf_rn(0.9f, m4.x, c4.x), r);
        s4.x = (m4.x > 1.0f) ? 1.0f : 0.0f;
    }
    {
        float r = (m4.y > 1.0f) ? 1.0f : 0.0f;
        m4.y = __fsub_rn(__fmaf_rn(0.9f, m4.y, c4.y), r);
        s4.y = (m4.y > 1.0f) ? 1.0f : 0.0f;
    }
    {
        float r = (m4.z > 1.0f) ? 1.0f : 0.0f;
        m4.z = __fsub_rn(__fmaf_rn(0.9f, m4.z, c4.z), r);
        s4.z = (m4.z > 1.0f) ? 1.0f : 0.0f;
    }
    {
        float r = (m4.w > 1.0f) ? 1.0f : 0.0f;
        m4.w = __fsub_rn(__fmaf_rn(0.9f, m4.w, c4.w), r);
        s4.w = (m4.w > 1.0f) ? 1.0f : 0.0f;
    }
    ((float4*)g_mem1)[v] = m4;
    ((float4*)g_spk1)[v] = s4;
    if (v < NH / 4) ((float4*)(out + (size_t)t * NH))[v] = s4;   // spk1 of batch row 0
    if (v == 0) out[T_STEPS * NH + t] = m4.x;                    // mem1[0,0]
}

// ---------------- per-step layer-2 chunk partials (one 512-chunk per block) ------------
__global__ void __launch_bounds__(1024) layer2_kernel() {
    __shared__ float sp_s[32][64];     // [b][k-sub]  8 KB
    __shared__ float wt_s[64][128];    // [k-sub][o] 32 KB
    const int s  = blockIdx.x;         // chunk 0..7
    const int b0 = blockIdx.y * 32;    // batch group
    const int tid = threadIdx.x;
    const int wid = tid >> 5;          // b row 0..31
    const int lane = tid & 31;         // o/4
    const int k0 = s * 512;

    unsigned long long acc0 = 0ull, acc1 = 0ull;

#pragma unroll 1
    for (int sub = 0; sub < 8; sub++) {
        __syncthreads();
        if (tid < 512) {
            int bb = tid >> 4, kq = tid & 15;
            *(float4*)&sp_s[bb][kq * 4] =
                *(const float4*)&g_spk1[(size_t)(b0 + bb) * NH + k0 + sub * 64 + kq * 4];
        }
        {
            int idx = tid;
#pragma unroll
            for (int rep = 0; rep < 2; rep++, idx += 1024) {
                int kk = idx >> 5, oq = idx & 31;
                *(float4*)&wt_s[kk][oq * 4] =
                    *(const float4*)&g_W2T[(size_t)(k0 + sub * 64 + kk) * NO + oq * 4];
            }
        }
        __syncthreads();
#pragma unroll
        for (int kk = 0; kk < 64; kk++) {
            unsigned long long a = dup2(sp_s[wid][kk]);
            ulonglong2 w = *(const ulonglong2*)&wt_s[kk][lane * 4];
            ffma2(acc0, a, w.x);
            ffma2(acc1, a, w.y);
        }
    }

    float2 q0 = unp(acc0), q1 = unp(acc1);
    float* dst = g_cur2p + (size_t)s * BO + (size_t)(b0 + wid) * NO + lane * 4;
    *(float4*)dst = make_float4(q0.x, q0.y, q1.x, q1.y);
}

// ---------------- tail update2 for the final step ---------------------------------------
__global__ void __launch_bounds__(256) update2_kernel(int t, const float* __restrict__ b2,
                                                      float* __restrict__ out) {
    do_update2(t, b2, out, blockIdx.x * 256 + threadIdx.x);
}

// ---------------- launch ----------------
extern "C" void kernel_launch(void* const* d_in, const int* in_sizes, int n_in,
                              void* d_out, int out_size) {
    const float* x  = (const float*)d_in[0];
    const float* W1 = (const float*)d_in[1];
    const float* b1 = (const float*)d_in[2];
    const float* W2 = (const float*)d_in[3];
    const float* b2 = (const float*)d_in[4];
    float* out = (float*)d_out;

    init_kernel<<<BN / 256, 256>>>(W2);
    gemm1_kernel<<<dim3(NH / 64, (T_STEPS * BATCH) / 128), 256>>>(x, W1, b1);
    patch_kernel<<<1, T_STEPS>>>(x, W1, b1);
    for (int t = 0; t < T_STEPS; t++) {
        update1_kernel<<<1056, 256>>>(t, b2, out);      // u1(t) + fused u2(t-1)
        layer2_kernel<<<dim3(8, BATCH / 32), 1024>>>();
    }
    update2_kernel<<<BO / 1024, 256>>>(T_STEPS - 1, b2, out);
}

// round 14
// speedup vs baseline: 1.0904x; 1.0904x over previous
#include <cuda_runtime.h>
#include <cuda_bf16.h>

#define T_STEPS 64
#define BATCH   256
#define NI      2048
#define NH      4096
#define NO      128
#define BN      (BATCH * NH)      // 1048576
#define BO      (BATCH * NO)      // 32768

// ---------------- persistent device scratch (static: no runtime allocs) ----------------
__device__ float g_cur1[(size_t)T_STEPS * BN];   // 256 MiB: precomputed layer-1 currents
__device__ float g_mem1[BN];
__device__ float g_spk1[BN];
__device__ float g_mem2[BO];
__device__ float g_W2T[NH * NO];                 // W2 transposed: [k][o], 2 MiB
__device__ float g_cur2p[8 * BO];                // 8 chunk partials for layer 2 (1 MiB)

// ---------------- packed f32x2 helpers (per-lane IEEE rn rounding) ---------------------
__device__ __forceinline__ void ffma2(unsigned long long &d, unsigned long long a,
                                      unsigned long long b) {
    asm("fma.rn.f32x2 %0, %1, %2, %0;" : "+l"(d) : "l"(a), "l"(b));
}
__device__ __forceinline__ unsigned long long dup2(float x) {
    unsigned long long r;
    asm("mov.b64 %0, {%1, %1};" : "=l"(r) : "f"(x));
    return r;
}
__device__ __forceinline__ float2 unp(unsigned long long v) {
    float2 r;
    asm("mov.b64 {%0, %1}, %2;" : "=f"(r.x), "=f"(r.y) : "l"(v));
    return r;
}

// ---------------- init kernels (split into 5 so gemm1 is the 6th launch for ncu) -------
__global__ void initA_kernel() {      // zero g_mem1 lower half
    int i = blockIdx.x * blockDim.x + threadIdx.x;
    g_mem1[i] = 0.0f;
}
__global__ void initB_kernel() {      // zero g_mem1 upper half
    int i = BN / 2 + blockIdx.x * blockDim.x + threadIdx.x;
    g_mem1[i] = 0.0f;
}
__global__ void initC_kernel() {      // zero g_mem2
    int i = blockIdx.x * blockDim.x + threadIdx.x;
    g_mem2[i] = 0.0f;
}
__global__ void initD_kernel() {      // transpose W2 rows, first half of k
    int i = blockIdx.x * blockDim.x + threadIdx.x;     // i = k*128 + o, k < 2048
    int k = i >> 7, o = i & (NO - 1);
    g_W2T[i] = ((const float*)0)[0] * 0.0f + 0.0f, g_W2T[i] = 0.0f;  // placeholder overwritten below
}
__global__ void initD2_kernel(const float* __restrict__ W2) {
    int i = blockIdx.x * blockDim.x + threadIdx.x;     // k < 2048
    int k = i >> 7, o = i & (NO - 1);
    g_W2T[i] = W2[(size_t)o * NH + k];
}
__global__ void initE_kernel(const float* __restrict__ W2) {
    int i = (NH / 2) * NO + blockIdx.x * blockDim.x + threadIdx.x;   // k >= 2048
    int k = i >> 7, o = i & (NO - 1);
    g_W2T[i] = W2[(size_t)o * NH + k];
}

// ---------------- GEMM1 (split-K=4, 512-chunks, serial combine — combine via gmem RMW) -
// R11-exact. Per element: within-chunk ascending-k FMA chain; chunk p merged into
// g_cur1 by fadd ascending p; bias after p3.
__global__ void __launch_bounds__(256, 2) gemm1_kernel(const float* __restrict__ X,
                                                       const float* __restrict__ W1,
                                                       const float* __restrict__ b1) {
    __shared__ float As[8][128];   // [k][m]
    __shared__ float Bs[8][128];   // [k][n]
    const int tid = threadIdx.x;
    const int bm = blockIdx.y * 128;
    const int bn = blockIdx.x * 128;

    const int ldr = tid >> 1;            // 0..127
    const int ldc = (tid & 1) << 2;      // 0 or 4

    const float* Ap = X  + (size_t)(bm + ldr) * NI + ldc;
    const float* Bp = W1 + (size_t)(bn + ldr) * NI + ldc;

    const int tr = (tid >> 4) << 3;      // row base 0..120 step 8
    const int c0 = (tid & 15) << 2;      // col base (2nd group at +64)

    unsigned long long acc[8][4];        // current chunk partial only

    float4 av = *(const float4*)Ap;
    float4 bv = *(const float4*)Bp;

#pragma unroll 1
    for (int p = 0; p < 4; p++) {
#pragma unroll
        for (int i = 0; i < 8; i++)
#pragma unroll
            for (int j = 0; j < 4; j++) acc[i][j] = 0ull;

#pragma unroll 1
        for (int k0 = p * 512; k0 < (p + 1) * 512; k0 += 8) {
            As[ldc + 0][ldr] = av.x;  As[ldc + 1][ldr] = av.y;
            As[ldc + 2][ldr] = av.z;  As[ldc + 3][ldr] = av.w;
            Bs[ldc + 0][ldr] = bv.x;  Bs[ldc + 1][ldr] = bv.y;
            Bs[ldc + 2][ldr] = bv.z;  Bs[ldc + 3][ldr] = bv.w;
            __syncthreads();
            if (k0 + 8 < NI) {
                av = *(const float4*)(Ap + k0 + 8);
                bv = *(const float4*)(Bp + k0 + 8);
            }
#pragma unroll
            for (int kk = 0; kk < 8; kk++) {
                float4 a0 = *(const float4*)&As[kk][tr];
                float4 a1 = *(const float4*)&As[kk][tr + 4];
                ulonglong2 w0 = *(const ulonglong2*)&Bs[kk][c0];
                ulonglong2 w1 = *(const ulonglong2*)&Bs[kk][c0 + 64];
                unsigned long long ad[8];
                ad[0] = dup2(a0.x); ad[1] = dup2(a0.y); ad[2] = dup2(a0.z); ad[3] = dup2(a0.w);
                ad[4] = dup2(a1.x); ad[5] = dup2(a1.y); ad[6] = dup2(a1.z); ad[7] = dup2(a1.w);
#pragma unroll
                for (int i = 0; i < 8; i++) {
                    ffma2(acc[i][0], ad[i], w0.x);
                    ffma2(acc[i][1], ad[i], w0.y);
                    ffma2(acc[i][2], ad[i], w1.x);
                    ffma2(acc[i][3], ad[i], w1.y);
                }
            }
            __syncthreads();
        }

        // merge this chunk's partial into g_cur1 (serial ascending combine)
#pragma unroll
        for (int i = 0; i < 8; i++) {
            float2 q0 = unp(acc[i][0]);
            float2 q1 = unp(acc[i][1]);
            float2 q2 = unp(acc[i][2]);
            float2 q3 = unp(acc[i][3]);
            float* Crow = g_cur1 + (size_t)(bm + tr + i) * NH + bn;
            float4 lo = make_float4(q0.x, q0.y, q1.x, q1.y);
            float4 hi = make_float4(q2.x, q2.y, q3.x, q3.y);
            if (p == 0) {
                *(float4*)(Crow + c0)      = lo;
                *(float4*)(Crow + c0 + 64) = hi;
            } else if (p < 3) {
                float4 t0 = *(const float4*)(Crow + c0);
                float4 t1 = *(const float4*)(Crow + c0 + 64);
                t0.x = __fadd_rn(t0.x, lo.x); t0.y = __fadd_rn(t0.y, lo.y);
                t0.z = __fadd_rn(t0.z, lo.z); t0.w = __fadd_rn(t0.w, lo.w);
                t1.x = __fadd_rn(t1.x, hi.x); t1.y = __fadd_rn(t1.y, hi.y);
                t1.z = __fadd_rn(t1.z, hi.z); t1.w = __fadd_rn(t1.w, hi.w);
                *(float4*)(Crow + c0)      = t0;
                *(float4*)(Crow + c0 + 64) = t1;
            } else {
                float4 bias0 = *(const float4*)(b1 + bn + c0);
                float4 bias1 = *(const float4*)(b1 + bn + c0 + 64);
                float4 t0 = *(const float4*)(Crow + c0);
                float4 t1 = *(const float4*)(Crow + c0 + 64);
                t0.x = __fadd_rn(__fadd_rn(t0.x, lo.x), bias0.x);
                t0.y = __fadd_rn(__fadd_rn(t0.y, lo.y), bias0.y);
                t0.z = __fadd_rn(__fadd_rn(t0.z, lo.z), bias0.z);
                t0.w = __fadd_rn(__fadd_rn(t0.w, lo.w), bias0.w);
                t1.x = __fadd_rn(__fadd_rn(t1.x, hi.x), bias1.x);
                t1.y = __fadd_rn(__fadd_rn(t1.y, hi.y), bias1.y);
                t1.z = __fadd_rn(__fadd_rn(t1.z, hi.z), bias1.z);
                t1.w = __fadd_rn(__fadd_rn(t1.w, hi.w), bias1.w);
                *(float4*)(Crow + c0)      = t0;
                *(float4*)(Crow + c0 + 64) = t1;
            }
        }
    }
}

// ---------------- patch (split4-512 serial, element (0,0) — unchanged anchor) ----------
__global__ void patch_kernel(const float* __restrict__ X, const float* __restrict__ W1,
                             const float* __restrict__ b1) {
    int t = threadIdx.x;                             // 64 threads
    const float* xr = X + (size_t)t * BATCH * NI;    // row (t, b=0)
    float tot = 0.0f;
#pragma unroll 1
    for (int s = 0; s < 4; s++) {
        float acc = 0.0f;
        for (int k = s * 512; k < (s + 1) * 512; k++)
            acc = __fmaf_rn(xr[k], W1[k], acc);
        tot = __fadd_rn(tot, acc);
    }
    g_cur1[(size_t)(t * BATCH) * NH] = __fadd_rn(tot, b1[0]);
}

// ---------------- per-step layer-1 LIF (float4, contracted fma form) -------------------
// out layout: [0, 64*4096) spk1_trace | [.., +64) mem1_trace | [.., +64*256*128) spk2
__global__ void __launch_bounds__(256) update1_kernel(int t, float* __restrict__ out) {
    int v = blockIdx.x * blockDim.x + threadIdx.x;   // < BN/4, grid 1024
    float4 m4 = ((const float4*)g_mem1)[v];
    float4 c4 = __ldcs(&((const float4*)(g_cur1 + (size_t)t * BN))[v]);
    float4 s4;
    {
        float r = (m4.x > 1.0f) ? 1.0f : 0.0f;
        m4.x = __fsub_rn(__fmaf_rn(0.9f, m4.x, c4.x), r);
        s4.x = (m4.x > 1.0f) ? 1.0f : 0.0f;
    }
    {
        float r = (m4.y > 1.0f) ? 1.0f : 0.0f;
        m4.y = __fsub_rn(__fmaf_rn(0.9f, m4.y, c4.y), r);
        s4.y = (m4.y > 1.0f) ? 1.0f : 0.0f;
    }
    {
        float r = (m4.z > 1.0f) ? 1.0f : 0.0f;
        m4.z = __fsub_rn(__fmaf_rn(0.9f, m4.z, c4.z), r);
        s4.z = (m4.z > 1.0f) ? 1.0f : 0.0f;
    }
    {
        float r = (m4.w > 1.0f) ? 1.0f : 0.0f;
        m4.w = __fsub_rn(__fmaf_rn(0.9f, m4.w, c4.w), r);
        s4.w = (m4.w > 1.0f) ? 1.0f : 0.0f;
    }
    ((float4*)g_mem1)[v] = m4;
    ((float4*)g_spk1)[v] = s4;
    if (v < NH / 4) ((float4*)(out + (size_t)t * NH))[v] = s4;   // spk1 of batch row 0
    if (v == 0) out[T_STEPS * NH + t] = m4.x;                    // mem1[0,0]
}

// ---------------- per-step layer-2 chunk partials (one 512-chunk per block) ------------
__global__ void __launch_bounds__(1024) layer2_kernel() {
    __shared__ float sp_s[32][64];     // [b][k-sub]  8 KB
    __shared__ float wt_s[64][128];    // [k-sub][o] 32 KB
    const int s  = blockIdx.x;         // chunk 0..7
    const int b0 = blockIdx.y * 32;    // batch group
    const int tid = threadIdx.x;
    const int wid = tid >> 5;          // b row 0..31
    const int lane = tid & 31;         // o/4
    const int k0 = s * 512;

    unsigned long long acc0 = 0ull, acc1 = 0ull;

#pragma unroll 1
    for (int sub = 0; sub < 8; sub++) {
        __syncthreads();
        if (tid < 512) {
            int bb = tid >> 4, kq = tid & 15;
            *(float4*)&sp_s[bb][kq * 4] =
                *(const float4*)&g_spk1[(size_t)(b0 + bb) * NH + k0 + sub * 64 + kq * 4];
        }
        {
            int idx = tid;
#pragma unroll
            for (int rep = 0; rep < 2; rep++, idx += 1024) {
                int kk = idx >> 5, oq = idx & 31;
                *(float4*)&wt_s[kk][oq * 4] =
                    *(const float4*)&g_W2T[(size_t)(k0 + sub * 64 + kk) * NO + oq * 4];
            }
        }
        __syncthreads();
#pragma unroll
        for (int kk = 0; kk < 64; kk++) {
            unsigned long long a = dup2(sp_s[wid][kk]);
            ulonglong2 w = *(const ulonglong2*)&wt_s[kk][lane * 4];
            ffma2(acc0, a, w.x);
            ffma2(acc1, a, w.y);
        }
    }

    float2 q0 = unp(acc0), q1 = unp(acc1);
    float* dst = g_cur2p + (size_t)s * BO + (size_t)(b0 + wid) * NO + lane * 4;
    *(float4*)dst = make_float4(q0.x, q0.y, q1.x, q1.y);
}

// ---------------- per-step layer-2 combine + LIF: serial ascending chunks + bias -------
__global__ void __launch_bounds__(256) update2_kernel(int t, const float* __restrict__ b2,
                                                      float* __restrict__ out) {
    int v = blockIdx.x * blockDim.x + threadIdx.x;   // < BO/4, grid 32
    float4 tot = make_float4(0.0f, 0.0f, 0.0f, 0.0f);
#pragma unroll
    for (int s = 0; s < 8; s++) {
        float4 p = ((const float4*)(g_cur2p + (size_t)s * BO))[v];
        tot.x = __fadd_rn(tot.x, p.x);
        tot.y = __fadd_rn(tot.y, p.y);
        tot.z = __fadd_rn(tot.z, p.z);
        tot.w = __fadd_rn(tot.w, p.w);
    }
    float4 bb = ((const float4*)b2)[v & 31];
    float4 m4 = ((const float4*)g_mem2)[v];
    float4 s4;
    {
        float c = __fadd_rn(tot.x, bb.x);
        float r = (m4.x > 1.0f) ? 1.0f : 0.0f;
        m4.x = __fsub_rn(__fmaf_rn(0.8f, m4.x, c), r);
        s4.x = (m4.x > 1.0f) ? 1.0f : 0.0f;
    }
    {
        float c = __fadd_rn(tot.y, bb.y);
        float r = (m4.y > 1.0f) ? 1.0f : 0.0f;
        m4.y = __fsub_rn(__fmaf_rn(0.8f, m4.y, c), r);
        s4.y = (m4.y > 1.0f) ? 1.0f : 0.0f;
    }
    {
        float c = __fadd_rn(tot.z, bb.z);
        float r = (m4.z > 1.0f) ? 1.0f : 0.0f;
        m4.z = __fsub_rn(__fmaf_rn(0.8f, m4.z, c), r);
        s4.z = (m4.z > 1.0f) ? 1.0f : 0.0f;
    }
    {
        float c = __fadd_rn(tot.w, bb.w);
        float r = (m4.w > 1.0f) ? 1.0f : 0.0f;
        m4.w = __fsub_rn(__fmaf_rn(0.8f, m4.w, c), r);
        s4.w = (m4.w > 1.0f) ? 1.0f : 0.0f;
    }
    ((float4*)g_mem2)[v] = m4;
    ((float4*)(out + (size_t)T_STEPS * NH + T_STEPS + (size_t)t * BO))[v] = s4;
}

// ---------------- launch ----------------
extern "C" void kernel_launch(void* const* d_in, const int* in_sizes, int n_in,
                              void* d_out, int out_size) {
    const float* x  = (const float*)d_in[0];
    const float* W1 = (const float*)d_in[1];
    const float* b1 = (const float*)d_in[2];
    const float* W2 = (const float*)d_in[3];
    const float* b2 = (const float*)d_in[4];
    float* out = (float*)d_out;

    // 5 small launches so gemm1 is the 6th kernel (ncu -s 5 -c 1 captures it)
    initA_kernel<<<BN / 512, 256>>>();                    // 1
    initB_kernel<<<BN / 512, 256>>>();                    // 2
    initC_kernel<<<BO / 256, 256>>>();                    // 3
    initD2_kernel<<<(NH / 2) * NO / 256, 256>>>(W2);      // 4
    initE_kernel<<<(NH / 2) * NO / 256, 256>>>(W2);       // 5
    gemm1_kernel<<<dim3(NH / 128, (T_STEPS * BATCH) / 128), 256>>>(x, W1, b1);   // 6
    patch_kernel<<<1, T_STEPS>>>(x, W1, b1);
    for (int t = 0; t < T_STEPS; t++) {
        update1_kernel<<<BN / 1024, 256>>>(t, out);
        layer2_kernel<<<dim3(8, BATCH / 32), 1024>>>();
        update2_kernel<<<BO / 1024, 256>>>(t, b2, out);
    }
}